// round 10
// baseline (speedup 1.0000x reference)
#include <cuda_runtime.h>
#include <cuda_fp16.h>

// ---------------------------------------------------------------------------
// NetMHCpan BiLSTM:  pep BiLSTM (T=15) + HLA BiLSTM (T=372), H=1024,
// then MLP 4096 -> 4096 (relu) -> 1.
//
// Persistent cooperative kernel, 128 CTAs. Each CTA owns 8 hidden units of
// BOTH directions of the current phase (2 x 32 gate rows, fp16 in SMEM,
// 128 KB -> occupancy 1 -> all 128 CTAs co-resident). Directions interleaved
// per step so each dir's publish latency hides under the other's GEMV.
//
// Sync (low-pressure): producers publish h (st.cg) -> __threadfence ->
// red.global.gpu.add on ONE per-(dir,step) counter (fire-and-forget, no
// same-address full-atomic serialization). ONE thread per CTA polls the
// counter with nanosleep backoff (128 poll loads chip-wide on one line,
// instead of 16384 hammering it). After the barrier, 4 warps burst-fetch
// h via __ldcg with no per-flag gating.
// ---------------------------------------------------------------------------

#define H      1024
#define G4     4096
#define LPEP   15
#define LHLA   372
#define NCTA   128    // CTAs; each owns 8 HU of dir-f and 8 HU of dir-b
#define NHU    8      // hidden units per CTA per direction
#define NROWS  32     // gate rows per CTA per direction
#define NTHR   512    // 16 warps
#define NWARP  16
#define TMAX   400
#define SPIN_LIMIT (1u << 22)   // bounded spin: fail fast instead of deadlock

// SMEM: weights 2*32*1024 halves (131072 B) + h_f/h_b (8192 B) + gacc (256 B)
#define SMEM_BYTES (2 * NROWS * H * 2 + 2 * H * 4 + 2 * NROWS * 4)

struct Ptrs {
    const float* wih[4];
    const float* whh[4];
    const float* bih[4];
    const float* bhh[4];
};

// -------------------- device scratch (no allocations allowed) ---------------
__device__ float    g_xg[4 * LHLA * G4];    // input projections (24.4 MB)
__device__ float    g_h[4 * 2 * H];         // per-direction double-buffered h
__device__ unsigned g_cnt[4 * TMAX];        // per-(dir,step) arrival counters
__device__ float    g_h1[G4];               // MLP hidden activations

__device__ __forceinline__ float tanh_fast(float x) {
    float y;
    asm("tanh.approx.f32 %0, %1;" : "=f"(y) : "f"(x));
    return y;
}
__device__ __forceinline__ float sigmoid_fast(float x) {
    return fmaf(tanh_fast(0.5f * x), 0.5f, 0.5f);
}
__device__ __forceinline__ void red_add_gpu(unsigned* p, unsigned v) {
    asm volatile("red.global.gpu.add.u32 [%0], %1;" :: "l"(p), "r"(v) : "memory");
}

// ---------------------------------------------------------------------------
// Prep: blocks 0-63 compute xg[d][t][row] = x_t @ wih.T + bih + bhh;
// block 64: counters (NCTA at t=0, else 0); block 65: zero g_h.
// d: 0=pep_f 1=pep_b 2=hla_f 3=hla_b (backward dirs consume reversed input).
// ---------------------------------------------------------------------------
__global__ void prep_kernel(const float* __restrict__ in_pep,
                            const float* __restrict__ in_hla,
                            Ptrs p)
{
    __shared__ float sx[LHLA * 21];    // 31.2 KB
    const int bid = blockIdx.x;
    const int tid = threadIdx.x;

    if (bid >= 64) {
        if (bid == 64) {
            for (int i = tid; i < 4 * TMAX; i += 256)
                g_cnt[i] = ((i % TMAX) == 0) ? (unsigned)NCTA : 0u;
        } else {
            for (int i = tid; i < 4 * 2 * H; i += 256) g_h[i] = 0.0f;
        }
        return;
    }

    const int d  = bid >> 4;          // direction
    const int rb = bid & 15;          // row block (256 rows each)
    const int T  = (d < 2) ? LPEP : LHLA;
    const float* src = (d < 2) ? in_pep : in_hla;
    const bool rev = (d & 1);

    for (int i = tid; i < T * 21; i += 256) {
        int t = i / 21, j = i - t * 21;
        int ts = rev ? (T - 1 - t) : t;
        sx[t * 21 + j] = src[ts * 21 + j];
    }
    __syncthreads();

    const int row = rb * 256 + tid;
    float w[21];
    const float* wp = p.wih[d] + (size_t)row * 21;
#pragma unroll
    for (int j = 0; j < 21; ++j) w[j] = wp[j];
    const float b = p.bih[d][row] + p.bhh[d][row];

    float* out = g_xg + (size_t)d * LHLA * G4 + row;
    for (int t = 0; t < T; ++t) {
        float acc = b;
#pragma unroll
        for (int j = 0; j < 21; ++j) acc = fmaf(w[j], sx[t * 21 + j], acc);
        out[(size_t)t * G4] = acc;
    }
}

// ---------------------------------------------------------------------------
// GEMV helper: warp computes its 2 gate rows of one direction.
// ---------------------------------------------------------------------------
__device__ __forceinline__ void gemv_dir(const __half2* wt_dir, const float* h_sm,
                                         float* gacc, int warp, int lane)
{
    // lane-local h chunk: 4 groups of 8 floats, h[g*256 + lane*8 .. +8]
    float hr[32];
#pragma unroll
    for (int g = 0; g < 4; ++g) {
        ((float4*)hr)[2 * g]     = ((const float4*)h_sm)[g * 64 + lane * 2];
        ((float4*)hr)[2 * g + 1] = ((const float4*)h_sm)[g * 64 + lane * 2 + 1];
    }
#pragma unroll
    for (int i = 0; i < 2; ++i) {
        const int r = warp * 2 + i;                       // r = g*8 + u
        const uint4* wrow = (const uint4*)(wt_dir + r * 512);
        float acc = 0.0f;
#pragma unroll
        for (int g = 0; g < 4; ++g) {
            uint4 wq = wrow[g * 32 + lane];   // cols g*256 + lane*8 .. +7
            float2 f0 = __half22float2(*(const __half2*)&wq.x);
            float2 f1 = __half22float2(*(const __half2*)&wq.y);
            float2 f2 = __half22float2(*(const __half2*)&wq.z);
            float2 f3 = __half22float2(*(const __half2*)&wq.w);
            acc = fmaf(f0.x, hr[8 * g + 0], acc);
            acc = fmaf(f0.y, hr[8 * g + 1], acc);
            acc = fmaf(f1.x, hr[8 * g + 2], acc);
            acc = fmaf(f1.y, hr[8 * g + 3], acc);
            acc = fmaf(f2.x, hr[8 * g + 4], acc);
            acc = fmaf(f2.y, hr[8 * g + 5], acc);
            acc = fmaf(f3.x, hr[8 * g + 6], acc);
            acc = fmaf(f3.y, hr[8 * g + 7], acc);
        }
        acc += __shfl_xor_sync(0xffffffffu, acc, 16);
        acc += __shfl_xor_sync(0xffffffffu, acc, 8);
        acc += __shfl_xor_sync(0xffffffffu, acc, 4);
        acc += __shfl_xor_sync(0xffffffffu, acc, 2);
        acc += __shfl_xor_sync(0xffffffffu, acc, 1);
        if (lane == 0) gacc[r] = acc;
    }
}

// ---------------------------------------------------------------------------
// Persistent BiLSTM kernel (512 threads, both directions interleaved).
// ---------------------------------------------------------------------------
__global__ void __launch_bounds__(NTHR, 1) lstm_kernel(Ptrs p)
{
    extern __shared__ unsigned char smem[];
    __half2* wt    = (__half2*)smem;                       // [2][32][512] half2
    float*   h_smf = (float*)(smem + 2 * NROWS * H * 2);   // [1024]
    float*   h_smb = h_smf + H;                            // [1024]
    float*   gaccf = h_smb + H;                            // [32]
    float*   gaccb = gaccf + NROWS;                        // [32]

    const int tid  = threadIdx.x;
    const int lane = tid & 31;
    const int warp = tid >> 5;          // 0..15
    const int cta  = blockIdx.x;        // 0..127: owns HU [8*cta, 8*cta+8)

    for (int phase = 0; phase < 2; ++phase) {
        const int df = 2 * phase, db = 2 * phase + 1;
        const int T  = phase ? LHLA : LPEP;

        // ---- load 2 dirs x 32 gate rows of whh into SMEM as fp16 ----
        for (int rr = warp; rr < 2 * NROWS; rr += NWARP) {
            const int x = rr >> 5;              // 0=f, 1=b
            const int r = rr & 31;
            const int g = r >> 3, u = r & 7;
            const float4* src = (const float4*)
                (p.whh[2 * phase + x] + ((size_t)(g * H + 8 * cta + u)) * H);
            __half2* dst = wt + (size_t)rr * 512;
            for (int k = lane; k < 256; k += 32) {
                float4 f = src[k];
                dst[2 * k]     = __floats2half2_rn(f.x, f.y);
                dst[2 * k + 1] = __floats2half2_rn(f.z, f.w);
            }
        }
        float c_f = 0.0f, c_b = 0.0f;     // warp0 lanes<8: c_f; warp1: c_b
        float* hbf = g_h + df * 2 * H;
        float* hbb = g_h + db * 2 * H;
        unsigned* cnf = g_cnt + df * TMAX;
        unsigned* cnb = g_cnt + db * TMAX;
        const float* xgf = g_xg + (size_t)df * LHLA * G4;
        const float* xgb = g_xg + (size_t)db * LHLA * G4;
        __syncthreads();

        for (int t = 0; t < T; ++t) {
            // prefetch xg for both dirs (independent of h)
            float xf0=0.f, xf1=0.f, xf2=0.f, xf3=0.f;
            float xb0=0.f, xb1=0.f, xb2=0.f, xb3=0.f;
            if (warp == 0 && lane < NHU) {
                const float* xp = xgf + (size_t)t * G4 + 8 * cta + lane;
                xf0 = __ldg(xp);         xf1 = __ldg(xp + H);
                xf2 = __ldg(xp + 2 * H); xf3 = __ldg(xp + 3 * H);
            }
            if (warp == 1 && lane < NHU) {
                const float* xp = xgb + (size_t)t * G4 + 8 * cta + lane;
                xb0 = __ldg(xp);         xb1 = __ldg(xp + H);
                xb2 = __ldg(xp + 2 * H); xb3 = __ldg(xp + 3 * H);
            }

            // ---- detect f(t): ONE thread polls aggregated counter ----
            if (warp == 6 && lane == 0) {
                volatile unsigned* c = (volatile unsigned*)&cnf[t];
                unsigned spins = 0;
                while (*c < (unsigned)NCTA && ++spins < SPIN_LIMIT)
                    __nanosleep(64);
                __threadfence();                        // acquire
            }
            __syncthreads();                            // S0f: f(t) ready

            // ---- burst-fetch h_f(t) (warps 2-5, no gating) ----
            if (warp >= 2 && warp < 6) {
                const int q = tid - 64;                 // 0..127
                const float4* hs = (const float4*)(hbf + (t & 1) * H + q * NHU);
                float4 a = __ldcg(hs), b = __ldcg(hs + 1);
                float4* dst = (float4*)(h_smf + q * NHU);
                dst[0] = a; dst[1] = b;
            }
            __syncthreads();                            // S1f: h_f in SMEM

            gemv_dir(wt, h_smf, gaccf, warp, lane);     // dir f
            __syncthreads();                            // S2f: gaccf ready

            // warp0: cell_f + publish f(t+1)
            if (warp == 0) {
                if (lane < NHU) {
                    float zi = gaccf[0 * 8 + lane] + xf0;
                    float zf = gaccf[1 * 8 + lane] + xf1;
                    float zg = gaccf[2 * 8 + lane] + xf2;
                    float zo = gaccf[3 * 8 + lane] + xf3;
                    c_f = fmaf(sigmoid_fast(zf), c_f,
                               sigmoid_fast(zi) * tanh_fast(zg));
                    float hn = sigmoid_fast(zo) * tanh_fast(c_f);
                    __stcg(&hbf[((t + 1) & 1) * H + 8 * cta + lane], hn);
                }
                __threadfence();                        // release
                __syncwarp();
                if (lane == 0) red_add_gpu(&cnf[t + 1], 1u);
            }

            // ---- detect b(t) (published one GEMV ago -> mostly hidden) ----
            if (warp == 7 && lane == 0) {
                volatile unsigned* c = (volatile unsigned*)&cnb[t];
                unsigned spins = 0;
                while (*c < (unsigned)NCTA && ++spins < SPIN_LIMIT)
                    __nanosleep(64);
                __threadfence();
            }
            __syncthreads();                            // S0b

            if (warp >= 2 && warp < 6) {
                const int q = tid - 64;
                const float4* hs = (const float4*)(hbb + (t & 1) * H + q * NHU);
                float4 a = __ldcg(hs), b = __ldcg(hs + 1);
                float4* dst = (float4*)(h_smb + q * NHU);
                dst[0] = a; dst[1] = b;
            }
            __syncthreads();                            // S1b

            gemv_dir(wt + NROWS * 512, h_smb, gaccb, warp, lane);   // dir b
            __syncthreads();                            // S2b

            // warp1: cell_b + publish b(t+1)
            if (warp == 1) {
                if (lane < NHU) {
                    float zi = gaccb[0 * 8 + lane] + xb0;
                    float zf = gaccb[1 * 8 + lane] + xb1;
                    float zg = gaccb[2 * 8 + lane] + xb2;
                    float zo = gaccb[3 * 8 + lane] + xb3;
                    c_b = fmaf(sigmoid_fast(zf), c_b,
                               sigmoid_fast(zi) * tanh_fast(zg));
                    float hn = sigmoid_fast(zo) * tanh_fast(c_b);
                    __stcg(&hbb[((t + 1) & 1) * H + 8 * cta + lane], hn);
                }
                __threadfence();
                __syncwarp();
                if (lane == 0) red_add_gpu(&cnb[t + 1], 1u);
            }
        }
        __syncthreads();               // all reads of wt done before reload
    }
}

// ---------------------------------------------------------------------------
// MLP: h1 = relu(x @ w1.T + b1), y = h1 @ w2.T + b2.
// x = [pep_f, pep_b, hla_f, hla_b]; pep finals in buf 1 (T=15), hla in buf 0.
// ---------------------------------------------------------------------------
__global__ void mlp1_kernel(const float* __restrict__ w1, const float* __restrict__ b1)
{
    __shared__ float sx[G4];
    const int tid = threadIdx.x, lane = tid & 31, warp = tid >> 5;

    for (int k = tid; k < G4; k += 256) {
        int dd = k >> 10;
        int kk = k & 1023;
        int buf = (dd < 2) ? 1 : 0;    // pep T=15 -> buf 1, hla T=372 -> buf 0
        sx[k] = g_h[dd * 2 * H + buf * H + kk];
    }
    __syncthreads();

#pragma unroll
    for (int rep = 0; rep < 2; ++rep) {
        const int j = blockIdx.x * 16 + rep * 8 + warp;
        const float* wrow = w1 + (size_t)j * G4;
        float acc = 0.0f;
#pragma unroll 8
        for (int i = 0; i < 128; ++i)
            acc = fmaf(wrow[i * 32 + lane], sx[i * 32 + lane], acc);
        acc += __shfl_xor_sync(0xffffffffu, acc, 16);
        acc += __shfl_xor_sync(0xffffffffu, acc, 8);
        acc += __shfl_xor_sync(0xffffffffu, acc, 4);
        acc += __shfl_xor_sync(0xffffffffu, acc, 2);
        acc += __shfl_xor_sync(0xffffffffu, acc, 1);
        if (lane == 0) g_h1[j] = fmaxf(acc + b1[j], 0.0f);
    }
}

__global__ void mlp2_kernel(const float* __restrict__ w2, const float* __restrict__ b2,
                            float* __restrict__ out)
{
    __shared__ float red[32];
    const int tid = threadIdx.x, lane = tid & 31, warp = tid >> 5;
    float acc = 0.0f;
    for (int k = tid; k < G4; k += 1024)
        acc = fmaf(g_h1[k], w2[k], acc);
    acc += __shfl_xor_sync(0xffffffffu, acc, 16);
    acc += __shfl_xor_sync(0xffffffffu, acc, 8);
    acc += __shfl_xor_sync(0xffffffffu, acc, 4);
    acc += __shfl_xor_sync(0xffffffffu, acc, 2);
    acc += __shfl_xor_sync(0xffffffffu, acc, 1);
    if (lane == 0) red[warp] = acc;
    __syncthreads();
    if (warp == 0) {
        float v = red[lane];
        v += __shfl_xor_sync(0xffffffffu, v, 16);
        v += __shfl_xor_sync(0xffffffffu, v, 8);
        v += __shfl_xor_sync(0xffffffffu, v, 4);
        v += __shfl_xor_sync(0xffffffffu, v, 2);
        v += __shfl_xor_sync(0xffffffffu, v, 1);
        if (lane == 0) out[0] = v + b2[0];
    }
}

// ---------------------------------------------------------------------------
extern "C" void kernel_launch(void* const* d_in, const int* in_sizes, int n_in,
                              void* d_out, int out_size)
{
    (void)in_sizes; (void)n_in; (void)out_size;

    const float* in_pep = (const float*)d_in[0];
    const float* in_hla = (const float*)d_in[1];

    Ptrs p;
    // input order: [wih, whh, bih, bhh] for pep_f, pep_b, hla_f, hla_b
    for (int d = 0; d < 4; ++d) {
        p.wih[d] = (const float*)d_in[2 + 4 * d];
        p.whh[d] = (const float*)d_in[3 + 4 * d];
        p.bih[d] = (const float*)d_in[4 + 4 * d];
        p.bhh[d] = (const float*)d_in[5 + 4 * d];
    }
    const float* w1 = (const float*)d_in[18];
    const float* b1 = (const float*)d_in[19];
    const float* w2 = (const float*)d_in[20];
    const float* b2 = (const float*)d_in[21];

    cudaFuncSetAttribute(lstm_kernel, cudaFuncAttributeMaxDynamicSharedMemorySize,
                         SMEM_BYTES);

    prep_kernel<<<66, 256>>>(in_pep, in_hla, p);
    lstm_kernel<<<NCTA, NTHR, SMEM_BYTES>>>(p);
    mlp1_kernel<<<256, 256>>>(w1, b1);
    mlp2_kernel<<<1, 1024>>>(w2, b2, (float*)d_out);
}

// round 11
// speedup vs baseline: 1.2534x; 1.2534x over previous
#include <cuda_runtime.h>
#include <cuda_fp16.h>

// ---------------------------------------------------------------------------
// NetMHCpan BiLSTM:  pep BiLSTM (T=15) + HLA BiLSTM (T=372), H=1024,
// then MLP 4096 -> 4096 (relu) -> 1.
//
// Persistent cooperative kernel, 128 CTAs. Each CTA owns 8 hidden units of
// BOTH phase directions. UNIT-PER-WARP: warp w computes all 4 gate rows of
// unit w (dir f = warps 0-7, dir b = warps 8-15), the LSTM cell (lane 0),
// and publishes immediately -- no CTA-wide barrier after the GEMV, no lone
// publisher warp. The two direction groups run fully concurrently, synced
// only by per-group named barriers (bar.sync 1/2, 256).
//
// Publish: lane0 st.cg h -> __threadfence -> smem atomicAdd; 8th warp of the
// group does ONE red.global.gpu.add on the per-(dir,step) counter (128 REDGs
// chip-wide per step). Detect: one poller thread per CTA per dir spins on the
// counter with nanosleep backoff, threadfence, named barrier, burst fetch.
// ---------------------------------------------------------------------------

#define H      1024
#define G4     4096
#define LPEP   15
#define LHLA   372
#define NCTA   128
#define NHU    8      // hidden units per CTA per direction
#define NROWS  32     // gate rows per CTA per direction
#define NTHR   512    // 16 warps: 0-7 dir f, 8-15 dir b
#define NWARP  16
#define TMAX   400
#define SPIN_LIMIT (1u << 22)

// SMEM: weights 2*32*1024 half (131072 B) + h_f/h_b double-parity (16384 B)
#define SMEM_BYTES (2 * NROWS * H * 2 + 2 * 2 * H * 4)

struct Ptrs {
    const float* wih[4];
    const float* whh[4];
    const float* bih[4];
    const float* bhh[4];
};

// -------------------- device scratch (no allocations allowed) ---------------
__device__ float    g_xg[4 * LHLA * G4];    // input projections (24.4 MB)
__device__ float    g_h[4 * 2 * H];         // per-direction double-buffered h
__device__ unsigned g_cnt[4 * TMAX];        // per-(dir,step) arrival counters
__device__ float    g_h1[G4];               // MLP hidden activations

__device__ __forceinline__ float tanh_fast(float x) {
    float y;
    asm("tanh.approx.f32 %0, %1;" : "=f"(y) : "f"(x));
    return y;
}
__device__ __forceinline__ float sigmoid_fast(float x) {
    return fmaf(tanh_fast(0.5f * x), 0.5f, 0.5f);
}
__device__ __forceinline__ void red_add_gpu(unsigned* p, unsigned v) {
    asm volatile("red.global.gpu.add.u32 [%0], %1;" :: "l"(p), "r"(v) : "memory");
}
#define GROUP_BAR(id) asm volatile("bar.sync %0, 256;" :: "r"(id) : "memory")

// ---------------------------------------------------------------------------
// Prep: blocks 0-63 compute xg[d][t][row] = x_t @ wih.T + bih + bhh;
// block 64: counters (NCTA at t=0, else 0); block 65: zero g_h.
// d: 0=pep_f 1=pep_b 2=hla_f 3=hla_b (backward dirs consume reversed input).
// ---------------------------------------------------------------------------
__global__ void prep_kernel(const float* __restrict__ in_pep,
                            const float* __restrict__ in_hla,
                            Ptrs p)
{
    __shared__ float sx[LHLA * 21];    // 31.2 KB
    const int bid = blockIdx.x;
    const int tid = threadIdx.x;

    if (bid >= 64) {
        if (bid == 64) {
            for (int i = tid; i < 4 * TMAX; i += 256)
                g_cnt[i] = ((i % TMAX) == 0) ? (unsigned)NCTA : 0u;
        } else {
            for (int i = tid; i < 4 * 2 * H; i += 256) g_h[i] = 0.0f;
        }
        return;
    }

    const int d  = bid >> 4;
    const int rb = bid & 15;
    const int T  = (d < 2) ? LPEP : LHLA;
    const float* src = (d < 2) ? in_pep : in_hla;
    const bool rev = (d & 1);

    for (int i = tid; i < T * 21; i += 256) {
        int t = i / 21, j = i - t * 21;
        int ts = rev ? (T - 1 - t) : t;
        sx[t * 21 + j] = src[ts * 21 + j];
    }
    __syncthreads();

    const int row = rb * 256 + tid;
    float w[21];
    const float* wp = p.wih[d] + (size_t)row * 21;
#pragma unroll
    for (int j = 0; j < 21; ++j) w[j] = wp[j];
    const float b = p.bih[d][row] + p.bhh[d][row];

    float* out = g_xg + (size_t)d * LHLA * G4 + row;
    for (int t = 0; t < T; ++t) {
        float acc = b;
#pragma unroll
        for (int j = 0; j < 21; ++j) acc = fmaf(w[j], sx[t * 21 + j], acc);
        out[(size_t)t * G4] = acc;
    }
}

// ---------------------------------------------------------------------------
// Persistent BiLSTM kernel: 512 threads, dir-f = warps 0-7, dir-b = 8-15.
// ---------------------------------------------------------------------------
__global__ void __launch_bounds__(NTHR, 1) lstm_kernel(Ptrs p)
{
    extern __shared__ unsigned char smem[];
    __half2* wt    = (__half2*)smem;                       // [2][32][512] half2
    float*   h_smf = (float*)(smem + 2 * NROWS * H * 2);   // [2][1024]
    float*   h_smb = h_smf + 2 * H;                        // [2][1024]
    __shared__ unsigned s_cnt[2];                          // per-group arrivals

    const int tid  = threadIdx.x;
    const int lane = tid & 31;
    const int warp = tid >> 5;
    const int cta  = blockIdx.x;
    const int grpb = (warp >= 8);       // 0 = dir f, 1 = dir b
    const int w    = warp & 7;          // unit within CTA slice
    const int qloc = tid & 255;         // thread index within group

    for (int phase = 0; phase < 2; ++phase) {
        const int d = 2 * phase + grpb;
        const int T = phase ? LHLA : LPEP;

        // ---- all threads: load 2 dirs x 32 gate rows of whh as fp16 ----
        for (int rr = warp; rr < 2 * NROWS; rr += NWARP) {
            const int x = rr >> 5;          // 0=f, 1=b
            const int r = rr & 31;          // g*8 + u
            const int g = r >> 3, u = r & 7;
            const float4* src = (const float4*)
                (p.whh[2 * phase + x] + ((size_t)(g * H + 8 * cta + u)) * H);
            __half2* dst = wt + (size_t)rr * 512;
            for (int k = lane; k < 256; k += 32) {
                float4 f = src[k];
                dst[2 * k]     = __floats2half2_rn(f.x, f.y);
                dst[2 * k + 1] = __floats2half2_rn(f.z, f.w);
            }
        }
        if (tid < 2) s_cnt[tid] = 0u;
        __syncthreads();                    // weights + counters ready

        // group-specific pointers
        float*    hb   = g_h + d * 2 * H;
        unsigned* cn   = g_cnt + d * TMAX;
        const float* xg = g_xg + (size_t)d * LHLA * G4;
        const __half2* wtd = wt + (grpb ? NROWS * 512 : 0);
        float* h_sm = grpb ? h_smb : h_smf;
        const int barid = 1 + grpb;
        float c_u = 0.0f;                   // cell state (lane 0 of each warp)

        for (int t = 0; t < T; ++t) {
            // lane0: prefetch this unit's 4 xg gate values
            float x0 = 0.f, x1 = 0.f, x2 = 0.f, x3 = 0.f;
            if (lane == 0) {
                const float* xp = xg + (size_t)t * G4 + 8 * cta + w;
                x0 = __ldg(xp);
                x1 = __ldg(xp + H);
                x2 = __ldg(xp + 2 * H);
                x3 = __ldg(xp + 3 * H);
            }

            // one poller per group: wait for all 128 CTAs' h(t)
            if (w == 0 && lane == 0) {
                volatile unsigned* c = (volatile unsigned*)&cn[t];
                unsigned spins = 0;
                while (*c < (unsigned)NCTA && ++spins < SPIN_LIMIT)
                    __nanosleep(32);
                __threadfence();            // acquire (proven pattern)
            }
            GROUP_BAR(barid);               // h(t) globally ready

            // burst fetch h(t): 256 threads x one float4 = 1024 floats
            {
                const float4* hs = (const float4*)(hb + (t & 1) * H);
                ((float4*)(h_sm + (t & 1) * H))[qloc] = __ldcg(hs + qloc);
            }
            GROUP_BAR(barid);               // h(t) in SMEM

            // ---- unit GEMV: 4 gate rows of unit w ----
            const float* hsv = h_sm + (t & 1) * H;
            float hr[32];
#pragma unroll
            for (int g = 0; g < 4; ++g) {
                ((float4*)hr)[2 * g]     = ((const float4*)hsv)[g * 64 + lane * 2];
                ((float4*)hr)[2 * g + 1] = ((const float4*)hsv)[g * 64 + lane * 2 + 1];
            }
            float a0 = 0.f, a1 = 0.f, a2 = 0.f, a3 = 0.f;
#pragma unroll
            for (int g = 0; g < 4; ++g) {
                float* ap = (g == 0) ? &a0 : (g == 1) ? &a1 : (g == 2) ? &a2 : &a3;
                const uint4* wrow = (const uint4*)(wtd + (size_t)(g * 8 + w) * 512);
                float acc = 0.0f;
#pragma unroll
                for (int c4 = 0; c4 < 4; ++c4) {
                    uint4 wq = wrow[c4 * 32 + lane];   // cols c4*256+lane*8..+7
                    float2 f0 = __half22float2(*(const __half2*)&wq.x);
                    float2 f1 = __half22float2(*(const __half2*)&wq.y);
                    float2 f2 = __half22float2(*(const __half2*)&wq.z);
                    float2 f3 = __half22float2(*(const __half2*)&wq.w);
                    acc = fmaf(f0.x, hr[8 * c4 + 0], acc);
                    acc = fmaf(f0.y, hr[8 * c4 + 1], acc);
                    acc = fmaf(f1.x, hr[8 * c4 + 2], acc);
                    acc = fmaf(f1.y, hr[8 * c4 + 3], acc);
                    acc = fmaf(f2.x, hr[8 * c4 + 4], acc);
                    acc = fmaf(f2.y, hr[8 * c4 + 5], acc);
                    acc = fmaf(f3.x, hr[8 * c4 + 6], acc);
                    acc = fmaf(f3.y, hr[8 * c4 + 7], acc);
                }
                *ap = acc;
            }
#pragma unroll
            for (int s = 16; s >= 1; s >>= 1) {
                a0 += __shfl_xor_sync(0xffffffffu, a0, s);
                a1 += __shfl_xor_sync(0xffffffffu, a1, s);
                a2 += __shfl_xor_sync(0xffffffffu, a2, s);
                a3 += __shfl_xor_sync(0xffffffffu, a3, s);
            }

            // lane0: cell + immediate publish (no barrier after GEMV!)
            if (lane == 0) {
                float zi = a0 + x0, zf = a1 + x1, zg = a2 + x2, zo = a3 + x3;
                c_u = fmaf(sigmoid_fast(zf), c_u,
                           sigmoid_fast(zi) * tanh_fast(zg));
                float hn = sigmoid_fast(zo) * tanh_fast(c_u);
                __stcg(&hb[((t + 1) & 1) * H + 8 * cta + w], hn);
                __threadfence();            // release h before arrival
                unsigned old = atomicAdd(&s_cnt[grpb], 1u);
                if (old == (unsigned)(8 * t + 7))      // 8th warp of this step
                    red_add_gpu(&cn[t + 1], 1u);
            }
        }
        __syncthreads();                    // wt reads done before reload
    }
}

// ---------------------------------------------------------------------------
// MLP: h1 = relu(x @ w1.T + b1), y = h1 @ w2.T + b2.
// x = [pep_f, pep_b, hla_f, hla_b]; pep finals in buf 1 (T=15), hla in buf 0.
// ---------------------------------------------------------------------------
__global__ void mlp1_kernel(const float* __restrict__ w1, const float* __restrict__ b1)
{
    __shared__ float sx[G4];
    const int tid = threadIdx.x, lane = tid & 31, warp = tid >> 5;

    for (int k = tid; k < G4; k += 256) {
        int dd = k >> 10;
        int kk = k & 1023;
        int buf = (dd < 2) ? 1 : 0;    // pep T=15 -> buf 1, hla T=372 -> buf 0
        sx[k] = g_h[dd * 2 * H + buf * H + kk];
    }
    __syncthreads();

#pragma unroll
    for (int rep = 0; rep < 2; ++rep) {
        const int j = blockIdx.x * 16 + rep * 8 + warp;
        const float* wrow = w1 + (size_t)j * G4;
        float acc = 0.0f;
#pragma unroll 8
        for (int i = 0; i < 128; ++i)
            acc = fmaf(wrow[i * 32 + lane], sx[i * 32 + lane], acc);
        acc += __shfl_xor_sync(0xffffffffu, acc, 16);
        acc += __shfl_xor_sync(0xffffffffu, acc, 8);
        acc += __shfl_xor_sync(0xffffffffu, acc, 4);
        acc += __shfl_xor_sync(0xffffffffu, acc, 2);
        acc += __shfl_xor_sync(0xffffffffu, acc, 1);
        if (lane == 0) g_h1[j] = fmaxf(acc + b1[j], 0.0f);
    }
}

__global__ void mlp2_kernel(const float* __restrict__ w2, const float* __restrict__ b2,
                            float* __restrict__ out)
{
    __shared__ float red[32];
    const int tid = threadIdx.x, lane = tid & 31, warp = tid >> 5;
    float acc = 0.0f;
    for (int k = tid; k < G4; k += 1024)
        acc = fmaf(g_h1[k], w2[k], acc);
    acc += __shfl_xor_sync(0xffffffffu, acc, 16);
    acc += __shfl_xor_sync(0xffffffffu, acc, 8);
    acc += __shfl_xor_sync(0xffffffffu, acc, 4);
    acc += __shfl_xor_sync(0xffffffffu, acc, 2);
    acc += __shfl_xor_sync(0xffffffffu, acc, 1);
    if (lane == 0) red[warp] = acc;
    __syncthreads();
    if (warp == 0) {
        float v = red[lane];
        v += __shfl_xor_sync(0xffffffffu, v, 16);
        v += __shfl_xor_sync(0xffffffffu, v, 8);
        v += __shfl_xor_sync(0xffffffffu, v, 4);
        v += __shfl_xor_sync(0xffffffffu, v, 2);
        v += __shfl_xor_sync(0xffffffffu, v, 1);
        if (lane == 0) out[0] = v + b2[0];
    }
}

// ---------------------------------------------------------------------------
extern "C" void kernel_launch(void* const* d_in, const int* in_sizes, int n_in,
                              void* d_out, int out_size)
{
    (void)in_sizes; (void)n_in; (void)out_size;

    const float* in_pep = (const float*)d_in[0];
    const float* in_hla = (const float*)d_in[1];

    Ptrs p;
    // input order: [wih, whh, bih, bhh] for pep_f, pep_b, hla_f, hla_b
    for (int d = 0; d < 4; ++d) {
        p.wih[d] = (const float*)d_in[2 + 4 * d];
        p.whh[d] = (const float*)d_in[3 + 4 * d];
        p.bih[d] = (const float*)d_in[4 + 4 * d];
        p.bhh[d] = (const float*)d_in[5 + 4 * d];
    }
    const float* w1 = (const float*)d_in[18];
    const float* b1 = (const float*)d_in[19];
    const float* w2 = (const float*)d_in[20];
    const float* b2 = (const float*)d_in[21];

    cudaFuncSetAttribute(lstm_kernel, cudaFuncAttributeMaxDynamicSharedMemorySize,
                         SMEM_BYTES);

    prep_kernel<<<66, 256>>>(in_pep, in_hla, p);
    lstm_kernel<<<NCTA, NTHR, SMEM_BYTES>>>(p);
    mlp1_kernel<<<256, 256>>>(w1, b1);
    mlp2_kernel<<<1, 1024>>>(w2, b2, (float*)d_out);
}